// round 6
// baseline (speedup 1.0000x reference)
#include <cuda_runtime.h>
#include <math.h>

#define PI2F      6.2831853071795864769f
#define KEXP      (-0.5f * PI2F * PI2F * 1.44269504088896341f)   // -0.5*(2pi)^2*log2(e)
#define ZITTERF   1e-4f

// -------- device scratch (zero-initialized at module load) --------
__device__ float  g_f[8 * 3 * 768 * 5];    // feature accumulator [(bc*768+i)*5+m]
__device__ float  g_hsum[8 * 3 * 10];      // layer-1 means per bc
__device__ float  g_w[8 * 3 * 5];          // mixture weights logits_s[b][c][m]
__device__ unsigned int g_cnt[24];         // per-bc finished-block counters
__device__ unsigned int g_gcnt;            // finished-bc counter

__device__ __forceinline__ float ex2f(float x) {
    float y;
    asm("ex2.approx.ftz.f32 %0, %1;" : "=f"(y) : "f"(x));
    return y;
}

// Decode compact triangular index: for I in 0..23, J in (I>>1)..11. 156 tiles.
__device__ __forceinline__ void tri_decode(int bx, int& I, int& J) {
    int x = bx, i = 0;
    while (x >= 12 - (i >> 1)) { x -= 12 - (i >> 1); i++; }
    I = i; J = (i >> 1) + x;
}

// ====== Kernel B2f: symmetric feature matvec + fused layer1/MLP/gumbel tail ======
__global__ void __launch_bounds__(256, 2) kB2f(
        const float* __restrict__ xc, const float* __restrict__ yc,
        const float* __restrict__ mu, const float* __restrict__ inv_std,
        const float* __restrict__ W1, const float* __restrict__ b1,
        const float* __restrict__ unif,
        const float* __restrict__ W2, const float* __restrict__ b2,
        const float* __restrict__ W3, const float* __restrict__ b3,
        const float* __restrict__ W4, const float* __restrict__ b4,
        const float* __restrict__ W5, const float* __restrict__ b5) {
    int I, J;
    tri_decode(blockIdx.x, I, J);
    bool mir = (J > (I >> 1));
    int bc = blockIdx.y; int b = bc / 3, c = bc % 3;
    int i0 = I * 32, j0 = J * 64;

    __shared__ float4 s_ci[3][32];
    __shared__ float4 s_cj[3][64];
    __shared__ float  s_red[8][16][20];
    __shared__ float  s_h[10];
    __shared__ int    s_last, s_last2;
    __shared__ float  sA[8][30], sB_[8][10], sll[8][15], accw[8][15];

    int tx = threadIdx.x, ty = threadIdx.y;
    int tid = ty * 16 + tx;

    if (tid < 96) {
        int g = tid / 32, ii = tid % 32; int i = i0 + ii;
        float x = xc[(b * 768 + i) * 3 + c];
        if (g == 0) {
            float s0, c0, s1, c1;
            sincosf(PI2F * mu[0] * x, &s0, &c0);
            sincosf(PI2F * mu[1] * x, &s1, &c1);
            s_ci[0][ii] = make_float4(c0, s0, c1, s1);
        } else if (g == 1) {
            float s2, c2, s3, c3;
            sincosf(PI2F * mu[2] * x, &s2, &c2);
            sincosf(PI2F * mu[3] * x, &s3, &c3);
            s_ci[1][ii] = make_float4(c2, s2, c3, s3);
        } else {
            float s4, c4;
            sincosf(PI2F * mu[4] * x, &s4, &c4);
            s_ci[2][ii] = make_float4(c4, s4, x, yc[(b * 768 + i) * 3 + c]);
        }
    }
    if (tid < 192) {
        int g = tid / 64, jl = tid % 64; int j = j0 + jl;
        float x = xc[(b * 768 + j) * 3 + c];
        if (g == 0) {
            float s0, c0, s1, c1;
            sincosf(PI2F * mu[0] * x, &s0, &c0);
            sincosf(PI2F * mu[1] * x, &s1, &c1);
            s_cj[0][jl] = make_float4(c0, s0, c1, s1);
        } else if (g == 1) {
            float s2, c2, s3, c3;
            sincosf(PI2F * mu[2] * x, &s2, &c2);
            sincosf(PI2F * mu[3] * x, &s3, &c3);
            s_cj[1][jl] = make_float4(c2, s2, c3, s3);
        } else {
            float s4, c4;
            sincosf(PI2F * mu[4] * x, &s4, &c4);
            s_cj[2][jl] = make_float4(c4, s4, x, yc[(b * 768 + j) * 3 + c]);
        }
    }
    float a2[5];
#pragma unroll
    for (int m = 0; m < 5; m++) { float s = inv_std[m]; a2[m] = KEXP * s * s; }
    __syncthreads();

    float4 ci0[2], ci1[2], ci2[2]; float xi[2], yi[2];
#pragma unroll
    for (int r = 0; r < 2; r++) {
        int row = ty + 16 * r;
        ci0[r] = s_ci[0][row]; ci1[r] = s_ci[1][row]; ci2[r] = s_ci[2][row];
        xi[r] = ci2[r].z; yi[r] = ci2[r].w;
    }

    float facc[2][5] = {};
    float gacc[4][5] = {};
#pragma unroll
    for (int jj = 0; jj < 4; jj++) {
        int jl = tx + 16 * jj;
        float4 g0 = s_cj[0][jl], g1 = s_cj[1][jl], g2 = s_cj[2][jl];
        float xj = g2.z, yj = g2.w;
#pragma unroll
        for (int r = 0; r < 2; r++) {
            float d = xi[r] - xj, d2 = d * d;
            float base;
            base = ex2f(a2[0] * d2) * fmaf(ci0[r].x, g0.x, ci0[r].y * g0.y);
            facc[r][0] = fmaf(base, yj, facc[r][0]); gacc[jj][0] = fmaf(base, yi[r], gacc[jj][0]);
            base = ex2f(a2[1] * d2) * fmaf(ci0[r].z, g0.z, ci0[r].w * g0.w);
            facc[r][1] = fmaf(base, yj, facc[r][1]); gacc[jj][1] = fmaf(base, yi[r], gacc[jj][1]);
            base = ex2f(a2[2] * d2) * fmaf(ci1[r].x, g1.x, ci1[r].y * g1.y);
            facc[r][2] = fmaf(base, yj, facc[r][2]); gacc[jj][2] = fmaf(base, yi[r], gacc[jj][2]);
            base = ex2f(a2[3] * d2) * fmaf(ci1[r].z, g1.z, ci1[r].w * g1.w);
            facc[r][3] = fmaf(base, yj, facc[r][3]); gacc[jj][3] = fmaf(base, yi[r], gacc[jj][3]);
            base = ex2f(a2[4] * d2) * fmaf(ci2[r].x, g2.x, ci2[r].y * g2.y);
            facc[r][4] = fmaf(base, yj, facc[r][4]); gacc[jj][4] = fmaf(base, yi[r], gacc[jj][4]);
        }
    }

    // f_i: reduce over tx (lane bits 0..3)
#pragma unroll
    for (int off = 8; off; off >>= 1)
#pragma unroll
        for (int r = 0; r < 2; r++)
#pragma unroll
            for (int m = 0; m < 5; m++)
                facc[r][m] += __shfl_xor_sync(0xffffffffu, facc[r][m], off);
    if (tx == 0) {
#pragma unroll
        for (int r = 0; r < 2; r++)
#pragma unroll
            for (int m = 0; m < 5; m++)
                atomicAdd(&g_f[((size_t)bc * 768 + i0 + ty + 16 * r) * 5 + m], facc[r][m]);
    }

    if (mir) {
        // f_j: fold ty parity within warp, then cross-warp via shared
#pragma unroll
        for (int jj = 0; jj < 4; jj++)
#pragma unroll
            for (int m = 0; m < 5; m++)
                gacc[jj][m] += __shfl_xor_sync(0xffffffffu, gacc[jj][m], 16);
        int lane = tid & 31, w = tid >> 5;
        if (lane < 16) {
#pragma unroll
            for (int jj = 0; jj < 4; jj++)
#pragma unroll
                for (int m = 0; m < 5; m++)
                    s_red[w][lane][jj * 5 + m] = gacc[jj][m];
        }
        __syncthreads();
        for (int o = tid; o < 320; o += 256) {
            int jl = o / 5, m = o % 5;
            int txx = jl & 15, jjj = jl >> 4;
            float s = 0.f;
#pragma unroll
            for (int w2 = 0; w2 < 8; w2++) s += s_red[w2][txx][jjj * 5 + m];
            atomicAdd(&g_f[((size_t)bc * 768 + j0 + jl) * 5 + m], s);
        }
    }

    // ---- tail: last block of this bc does layer-1 + mean ----
    __threadfence();
    __syncthreads();
    if (tid == 0) s_last = (atomicAdd(&g_cnt[bc], 1u) == 155u);
    __syncthreads();
    if (!s_last) return;

    if (tid < 10) s_h[tid] = 0.f;
    __syncthreads();
    {
        float hl[10] = {};
        for (int i = tid; i < 768; i += 256) {
            const float* fp = &g_f[((size_t)bc * 768 + i) * 5];
            float f0 = __ldcg(fp), f1 = __ldcg(fp + 1), f2 = __ldcg(fp + 2),
                  f3 = __ldcg(fp + 3), f4 = __ldcg(fp + 4);
            float yiv = yc[(b * 768 + i) * 3 + c];
#pragma unroll
            for (int h = 0; h < 10; h++) {
                float w0 = W1[h*6+0], w1 = W1[h*6+1], w2 = W1[h*6+2], w3 = W1[h*6+3], w4 = W1[h*6+4];
                float wsum = w0 + w1 + w2 + w3 + w4;
                float v = b1[h];
                v = fmaf(w0, f0, v); v = fmaf(w1, f1, v); v = fmaf(w2, f2, v);
                v = fmaf(w3, f3, v); v = fmaf(w4, f4, v);
                v = fmaf(yiv, fmaf(ZITTERF, wsum, W1[h*6+5]), v);
                hl[h] += fmaxf(v, 0.f);
            }
        }
#pragma unroll
        for (int off = 16; off; off >>= 1)
#pragma unroll
            for (int h = 0; h < 10; h++)
                hl[h] += __shfl_xor_sync(0xffffffffu, hl[h], off);
        if ((tid & 31) == 0) {
#pragma unroll
            for (int h = 0; h < 10; h++)
                atomicAdd(&s_h[h], hl[h]);
        }
    }
    __syncthreads();
    if (tid < 10) g_hsum[bc * 10 + tid] = s_h[tid] * (1.0f / 768.0f);
    __threadfence();
    __syncthreads();
    if (tid == 0) s_last2 = (atomicAdd(&g_gcnt, 1u) == 23u);
    __syncthreads();
    if (!s_last2) return;

    // ---- global tail: MLP + gumbel-softmax, one warp per batch b ----
    {
        int w = tid >> 5, lane = tid & 31;   // w = batch index 0..7
        if (lane < 30) sA[w][lane] = __ldcg(&g_hsum[w * 30 + lane]);
        __syncwarp();
        if (lane < 10) {
            float v = b2[lane];
            for (int k = 0; k < 30; k++) v = fmaf(W2[lane * 30 + k], sA[w][k], v);
            sB_[w][lane] = fmaxf(v, 0.f);
        }
        __syncwarp();
        if (lane < 10) {
            float v = b3[lane];
            for (int k = 0; k < 10; k++) v = fmaf(W3[lane * 10 + k], sB_[w][k], v);
            sA[w][lane] = fmaxf(v, 0.f);
        }
        __syncwarp();
        if (lane < 10) {
            float v = b4[lane];
            for (int k = 0; k < 10; k++) v = fmaf(W4[lane * 10 + k], sA[w][k], v);
            sB_[w][lane] = fmaxf(v, 0.f);
        }
        __syncwarp();
        if (lane < 15) {
            float v = b5[lane];
            for (int k = 0; k < 10; k++) v = fmaf(W5[lane * 10 + k], sB_[w][k], v);
            sll[w][lane] = v;
            accw[w][lane] = 0.f;
        }
        __syncwarp();
        if (lane < 30) {
            int s = lane / 3, cc = lane % 3;
            const float* u = unif + ((w * 10 + s) * 3 + cc) * 5;
            float z[5];
            float mx = -1e30f;
#pragma unroll
            for (int m = 0; m < 5; m++) {
                float g = -logf(-logf(u[m] + 1e-20f));
                z[m] = (g + sll[w][cc * 5 + m]) * 10.0f;   // /TEMP, TEMP=0.1
                mx = fmaxf(mx, z[m]);
            }
            float sum = 0.f;
#pragma unroll
            for (int m = 0; m < 5; m++) { z[m] = expf(z[m] - mx); sum += z[m]; }
            float inv = 0.1f / sum;                        // /sum, then mean over ns=10
#pragma unroll
            for (int m = 0; m < 5; m++) atomicAdd(&accw[w][cc * 5 + m], z[m] * inv);
        }
        __syncwarp();
        if (lane < 15) g_w[w * 15 + lane] = accw[w][lane];
    }
}

// ====== Kernel D2: symmetric weighted output, triangular 32i x 64j tiles ======
__global__ void __launch_bounds__(256, 2) kD2(const float* __restrict__ xc,
                                              const float* __restrict__ mu,
                                              const float* __restrict__ inv_std,
                                              const float* __restrict__ likerr,
                                              float* __restrict__ out) {
    int tx = threadIdx.x, ty = threadIdx.y;
    int tid = ty * 16 + tx;

    // prologue: reset scratch for the next launch (before any early return)
    {
        int lb = (blockIdx.z * 24 + blockIdx.y) * 12 + blockIdx.x;
        if (lb < 360) g_f[lb * 256 + tid] = 0.f;
        else if (lb == 360) {
            if (tid < 24) g_cnt[tid] = 0u;
            if (tid == 24) g_gcnt = 0u;
        }
    }

    int J = blockIdx.x, I = blockIdx.y;
    int half = I >> 1;
    if (J < half) return;
    bool mir = (J > half);
    int b  = blockIdx.z;
    int i0 = I * 32;
    int j0 = J * 64;

    __shared__ float2 s_wci[3][5][32];   // premultiplied by mixture weight
    __shared__ float4 s_cj[3][3][64];    // [c][group][jl]: (m0,m1),(m2,m3),(m4,xj)
    __shared__ float  s_xi[3][32];
    __shared__ float  s_diag[3];
    __shared__ __align__(16) float s_m[64 * 100];  // mirror staging: row jl, 96 cols, pitch 100

    for (int idx = tid; idx < 480; idx += 256) {
        int c = idx / 160, r = idx % 160, m = r / 32, ii = r % 32;
        float x = xc[(b * 768 + i0 + ii) * 3 + c];
        float s, co;
        sincosf(PI2F * mu[m] * x, &s, &co);
        float wv = g_w[b * 15 + c * 5 + m];
        s_wci[c][m][ii] = make_float2(co * wv, s * wv);
    }
    if (tid < 192) {
        int c = tid / 64, jl = tid % 64; int j = j0 + jl;
        float x = xc[(b * 768 + j) * 3 + c];
        float s0, c0, s1, c1, s2, c2, s3, c3, s4, c4;
        sincosf(PI2F * mu[0] * x, &s0, &c0);
        sincosf(PI2F * mu[1] * x, &s1, &c1);
        sincosf(PI2F * mu[2] * x, &s2, &c2);
        sincosf(PI2F * mu[3] * x, &s3, &c3);
        sincosf(PI2F * mu[4] * x, &s4, &c4);
        s_cj[c][0][jl] = make_float4(c0, s0, c1, s1);
        s_cj[c][1][jl] = make_float4(c2, s2, c3, s3);
        s_cj[c][2][jl] = make_float4(c4, s4, x, 0.f);
    }
    if (tid < 96) { int c = tid / 32, ii = tid % 32; s_xi[c][ii] = xc[(b * 768 + i0 + ii) * 3 + c]; }
    if (tid < 3) { float l = fminf(fmaxf(likerr[tid], 0.1f), 1.0f); s_diag[tid] = ZITTERF + l * l; }

    float a2[5];
#pragma unroll
    for (int m = 0; m < 5; m++) { float s = inv_std[m]; a2[m] = KEXP * s * s; }

    __syncthreads();

    float2 wci[2][3][5]; float xi[2][3];
#pragma unroll
    for (int r = 0; r < 2; r++)
#pragma unroll
        for (int c = 0; c < 3; c++) {
            xi[r][c] = s_xi[c][ty + 16 * r];
#pragma unroll
            for (int m = 0; m < 5; m++) wci[r][c][m] = s_wci[c][m][ty + 16 * r];
        }

#pragma unroll
    for (int jj = 0; jj < 4; jj++) {
        int jl = tx + 16 * jj; int j = j0 + jl;
        float acc[2][3];
#pragma unroll
        for (int c = 0; c < 3; c++) {
            float4 g0 = s_cj[c][0][jl], g1 = s_cj[c][1][jl], g2 = s_cj[c][2][jl];
            float xj = g2.z;
#pragma unroll
            for (int r = 0; r < 2; r++) {
                float d = xi[r][c] - xj, d2 = d * d;
                float a;
                a = ex2f(a2[0] * d2) * fmaf(wci[r][c][0].x, g0.x, wci[r][c][0].y * g0.y);
                a = fmaf(ex2f(a2[1] * d2), fmaf(wci[r][c][1].x, g0.z, wci[r][c][1].y * g0.w), a);
                a = fmaf(ex2f(a2[2] * d2), fmaf(wci[r][c][2].x, g1.x, wci[r][c][2].y * g1.y), a);
                a = fmaf(ex2f(a2[3] * d2), fmaf(wci[r][c][3].x, g1.z, wci[r][c][3].y * g1.w), a);
                a = fmaf(ex2f(a2[4] * d2), fmaf(wci[r][c][4].x, g2.x, wci[r][c][4].y * g2.y), a);
                acc[r][c] = a;
            }
        }
#pragma unroll
        for (int r = 0; r < 2; r++) {
            int i = i0 + ty + 16 * r;
            if (i == j) { acc[r][0] += s_diag[0]; acc[r][1] += s_diag[1]; acc[r][2] += s_diag[2]; }
            float* o = out + ((size_t)(b * 768 + i) * 768 + j) * 3;
            o[0] = acc[r][0]; o[1] = acc[r][1]; o[2] = acc[r][2];
            if (mir) {
                int col = (ty + 16 * r) * 3;
                s_m[jl * 100 + col]     = acc[r][0];
                s_m[jl * 100 + col + 1] = acc[r][1];
                s_m[jl * 100 + col + 2] = acc[r][2];
            }
        }
    }

    if (mir) {
        __syncthreads();
        int jl = tid >> 2, q = tid & 3;
        const float* src = s_m + jl * 100 + 24 * q;
        float* dst = out + ((size_t)(b * 768 + j0 + jl)) * 2304 + i0 * 3 + 24 * q;
#pragma unroll
        for (int k = 0; k < 6; k++)
            ((float4*)dst)[k] = ((const float4*)src)[k];
    }
}

extern "C" void kernel_launch(void* const* d_in, const int* in_sizes, int n_in,
                              void* d_out, int out_size) {
    const float* xc      = (const float*)d_in[0];
    const float* yc      = (const float*)d_in[1];
    const float* mu      = (const float*)d_in[2];
    const float* inv_std = (const float*)d_in[3];
    const float* likerr  = (const float*)d_in[4];
    const float* unif    = (const float*)d_in[5];
    const float* W1 = (const float*)d_in[6];
    const float* b1 = (const float*)d_in[7];
    const float* W2 = (const float*)d_in[8];
    const float* b2 = (const float*)d_in[9];
    const float* W3 = (const float*)d_in[10];
    const float* b3 = (const float*)d_in[11];
    const float* W4 = (const float*)d_in[12];
    const float* b4 = (const float*)d_in[13];
    const float* W5 = (const float*)d_in[14];
    const float* b5 = (const float*)d_in[15];
    float* out = (float*)d_out;

    kB2f<<<dim3(156, 24), dim3(16, 16)>>>(xc, yc, mu, inv_std, W1, b1, unif,
                                          W2, b2, W3, b3, W4, b4, W5, b5);
    kD2<<<dim3(12, 24, 8), dim3(16, 16)>>>(xc, mu, inv_std, likerr, out);
}

// round 7
// speedup vs baseline: 1.3450x; 1.3450x over previous
#include <cuda_runtime.h>
#include <math.h>

#define PI2F      6.2831853071795864769f
#define KEXP      (-0.5f * PI2F * PI2F * 1.44269504088896341f)   // -0.5*(2pi)^2*log2(e)
#define ZITTERF   1e-4f

// -------- device scratch --------
__device__ float2 g_cs[8 * 3 * 5 * 768];   // [(b*3+c)*5+m][i] = (cos,sin) of 2*pi*mu_m*x
__device__ float  g_f[8 * 3 * 768 * 5];    // feature accumulator [(bc*768+i)*5+m]
__device__ float  g_hsum[8 * 3 * 10];      // layer-1 sums over i
__device__ float  g_w[8 * 3 * 5];          // mixture weights logits_s[b][c][m]
__device__ unsigned int g_cnt2;            // kB3f finished-block counter

__device__ __forceinline__ float ex2f(float x) {
    float y;
    asm("ex2.approx.ftz.f32 %0, %1;" : "=f"(y) : "f"(x));
    return y;
}

// ================= Kernel A: sincos table + zero accumulators =================
__global__ void kA(const float* __restrict__ xc, const float* __restrict__ mu) {
    int idx = blockIdx.x * 256 + threadIdx.x;          // 92160 total
    int i  = idx % 768;
    int q  = idx / 768;     // 0..119
    int m  = q % 5;
    int bc = q / 5;         // 0..23
    int c  = bc % 3;
    int b  = bc / 3;
    float x = xc[(b * 768 + i) * 3 + c];
    float s, co;
    sincosf(PI2F * mu[m] * x, &s, &co);
    g_cs[idx] = make_float2(co, s);
    g_f[idx] = 0.f;                                   // exactly 92160 entries
    if (blockIdx.x == 0 && threadIdx.x < 240) g_hsum[threadIdx.x] = 0.f;
    if (idx == 0) g_cnt2 = 0u;
}

// ====== Kernel B2: symmetric feature matvec, triangular tiles 32i x 64j ======
__global__ void __launch_bounds__(256) kB2(const float* __restrict__ xc,
                                           const float* __restrict__ yc,
                                           const float* __restrict__ inv_std) {
    int J = blockIdx.x, I = blockIdx.y;
    int half = I >> 1;
    if (J < half) return;
    bool mir = (J > half);
    int bc = blockIdx.z; int b = bc / 3, c = bc % 3;
    int i0 = I * 32, j0 = J * 64;

    __shared__ float4 s_ci[3][32];
    __shared__ float4 s_cj[3][64];
    __shared__ float  s_red[8][16][20];

    int tx = threadIdx.x, ty = threadIdx.y;
    int tid = ty * 16 + tx;
    const float2* csb = g_cs + (size_t)bc * 5 * 768;

    if (tid < 96) {
        int g = tid / 32, ii = tid % 32; int i = i0 + ii;
        if (g == 0)      { float2 u = csb[i],         v = csb[768 + i];     s_ci[0][ii] = make_float4(u.x, u.y, v.x, v.y); }
        else if (g == 1) { float2 u = csb[2*768 + i], v = csb[3*768 + i];   s_ci[1][ii] = make_float4(u.x, u.y, v.x, v.y); }
        else             { float2 u = csb[4*768 + i];
                           s_ci[2][ii] = make_float4(u.x, u.y, xc[(b*768+i)*3+c], yc[(b*768+i)*3+c]); }
    }
    if (tid < 192) {
        int g = tid / 64, jl = tid % 64; int j = j0 + jl;
        if (g == 0)      { float2 u = csb[j],         v = csb[768 + j];     s_cj[0][jl] = make_float4(u.x, u.y, v.x, v.y); }
        else if (g == 1) { float2 u = csb[2*768 + j], v = csb[3*768 + j];   s_cj[1][jl] = make_float4(u.x, u.y, v.x, v.y); }
        else             { float2 u = csb[4*768 + j];
                           s_cj[2][jl] = make_float4(u.x, u.y, xc[(b*768+j)*3+c], yc[(b*768+j)*3+c]); }
    }
    float a2[5];
#pragma unroll
    for (int m = 0; m < 5; m++) { float s = inv_std[m]; a2[m] = KEXP * s * s; }
    __syncthreads();

    float4 ci0[2], ci1[2], ci2[2]; float xi[2], yi[2];
#pragma unroll
    for (int r = 0; r < 2; r++) {
        int row = ty + 16 * r;
        ci0[r] = s_ci[0][row]; ci1[r] = s_ci[1][row]; ci2[r] = s_ci[2][row];
        xi[r] = ci2[r].z; yi[r] = ci2[r].w;
    }

    float facc[2][5] = {};
    float gacc[4][5] = {};
#pragma unroll
    for (int jj = 0; jj < 4; jj++) {
        int jl = tx + 16 * jj;
        float4 g0 = s_cj[0][jl], g1 = s_cj[1][jl], g2 = s_cj[2][jl];
        float xj = g2.z, yj = g2.w;
#pragma unroll
        for (int r = 0; r < 2; r++) {
            float d = xi[r] - xj, d2 = d * d;
            float base;
            base = ex2f(a2[0] * d2) * fmaf(ci0[r].x, g0.x, ci0[r].y * g0.y);
            facc[r][0] = fmaf(base, yj, facc[r][0]); gacc[jj][0] = fmaf(base, yi[r], gacc[jj][0]);
            base = ex2f(a2[1] * d2) * fmaf(ci0[r].z, g0.z, ci0[r].w * g0.w);
            facc[r][1] = fmaf(base, yj, facc[r][1]); gacc[jj][1] = fmaf(base, yi[r], gacc[jj][1]);
            base = ex2f(a2[2] * d2) * fmaf(ci1[r].x, g1.x, ci1[r].y * g1.y);
            facc[r][2] = fmaf(base, yj, facc[r][2]); gacc[jj][2] = fmaf(base, yi[r], gacc[jj][2]);
            base = ex2f(a2[3] * d2) * fmaf(ci1[r].z, g1.z, ci1[r].w * g1.w);
            facc[r][3] = fmaf(base, yj, facc[r][3]); gacc[jj][3] = fmaf(base, yi[r], gacc[jj][3]);
            base = ex2f(a2[4] * d2) * fmaf(ci2[r].x, g2.x, ci2[r].y * g2.y);
            facc[r][4] = fmaf(base, yj, facc[r][4]); gacc[jj][4] = fmaf(base, yi[r], gacc[jj][4]);
        }
    }

    // f_i: reduce over tx (lane bits 0..3)
#pragma unroll
    for (int off = 8; off; off >>= 1)
#pragma unroll
        for (int r = 0; r < 2; r++)
#pragma unroll
            for (int m = 0; m < 5; m++)
                facc[r][m] += __shfl_xor_sync(0xffffffffu, facc[r][m], off);
    if (tx == 0) {
#pragma unroll
        for (int r = 0; r < 2; r++)
#pragma unroll
            for (int m = 0; m < 5; m++)
                atomicAdd(&g_f[((size_t)bc * 768 + i0 + ty + 16 * r) * 5 + m], facc[r][m]);
    }

    if (mir) {
        // f_j: fold ty parity within warp, then cross-warp via shared
#pragma unroll
        for (int jj = 0; jj < 4; jj++)
#pragma unroll
            for (int m = 0; m < 5; m++)
                gacc[jj][m] += __shfl_xor_sync(0xffffffffu, gacc[jj][m], 16);
        int lane = tid & 31, w = tid >> 5;
        if (lane < 16) {
#pragma unroll
            for (int jj = 0; jj < 4; jj++)
#pragma unroll
                for (int m = 0; m < 5; m++)
                    s_red[w][lane][jj * 5 + m] = gacc[jj][m];
        }
        __syncthreads();
        for (int o = tid; o < 320; o += 256) {
            int jl = o / 5, m = o % 5;
            int txx = jl & 15, jjj = jl >> 4;
            float s = 0.f;
#pragma unroll
            for (int w2 = 0; w2 < 8; w2++) s += s_red[w2][txx][jjj * 5 + m];
            atomicAdd(&g_f[((size_t)bc * 768 + j0 + jl) * 5 + m], s);
        }
    }
}

// ====== Kernel B3f: layer-1 + mean over i, fused MLP+Gumbel tail in last block ======
__global__ void __launch_bounds__(256) kB3f(const float* __restrict__ yc,
                                            const float* __restrict__ W1, const float* __restrict__ b1,
                                            const float* __restrict__ unif,
                                            const float* __restrict__ W2, const float* __restrict__ b2,
                                            const float* __restrict__ W3, const float* __restrict__ b3,
                                            const float* __restrict__ W4, const float* __restrict__ b4,
                                            const float* __restrict__ W5, const float* __restrict__ b5) {
    int bc = blockIdx.x; int b = bc / 3, c = bc % 3;
    int tid = threadIdx.x;
    __shared__ float sW[60], sB[10];
    __shared__ int   s_last;
    if (tid < 60) sW[tid] = W1[tid];
    if (tid < 10) sB[tid] = b1[tid];
    __syncthreads();

    float hl[10] = {};
    for (int i = tid; i < 768; i += 256) {
        const float* fp = &g_f[((size_t)bc * 768 + i) * 5];
        float f0 = fp[0], f1 = fp[1], f2 = fp[2], f3 = fp[3], f4 = fp[4];
        float yi = yc[(b * 768 + i) * 3 + c];
#pragma unroll
        for (int h = 0; h < 10; h++) {
            float w0 = sW[h*6+0], w1 = sW[h*6+1], w2 = sW[h*6+2], w3 = sW[h*6+3], w4 = sW[h*6+4];
            float wsum = w0 + w1 + w2 + w3 + w4;
            float v = sB[h];
            v = fmaf(w0, f0, v); v = fmaf(w1, f1, v); v = fmaf(w2, f2, v);
            v = fmaf(w3, f3, v); v = fmaf(w4, f4, v);
            v = fmaf(yi, fmaf(ZITTERF, wsum, sW[h*6+5]), v);
            hl[h] += fmaxf(v, 0.f);
        }
    }
#pragma unroll
    for (int off = 16; off; off >>= 1)
#pragma unroll
        for (int h = 0; h < 10; h++)
            hl[h] += __shfl_xor_sync(0xffffffffu, hl[h], off);
    if ((tid & 31) == 0) {
#pragma unroll
        for (int h = 0; h < 10; h++)
            atomicAdd(&g_hsum[bc * 10 + h], hl[h]);
    }

    // ---- last-block tail: MLP + Gumbel-softmax, one warp per batch b ----
    __threadfence();
    __syncthreads();
    if (tid == 0) s_last = (atomicAdd(&g_cnt2, 1u) == 23u);
    __syncthreads();
    if (!s_last) return;

    __shared__ float sA[8][30], sB_[8][10], sll[8][15], accw[8][15];
    int w = tid >> 5, lane = tid & 31;   // w = batch index 0..7
    if (lane < 30) sA[w][lane] = __ldcg(&g_hsum[w * 30 + lane]) * (1.0f / 768.0f);
    __syncwarp();
    if (lane < 10) {
        float v = b2[lane];
        for (int k = 0; k < 30; k++) v = fmaf(W2[lane * 30 + k], sA[w][k], v);
        sB_[w][lane] = fmaxf(v, 0.f);
    }
    __syncwarp();
    if (lane < 10) {
        float v = b3[lane];
        for (int k = 0; k < 10; k++) v = fmaf(W3[lane * 10 + k], sB_[w][k], v);
        sA[w][lane] = fmaxf(v, 0.f);
    }
    __syncwarp();
    if (lane < 10) {
        float v = b4[lane];
        for (int k = 0; k < 10; k++) v = fmaf(W4[lane * 10 + k], sA[w][k], v);
        sB_[w][lane] = fmaxf(v, 0.f);
    }
    __syncwarp();
    if (lane < 15) {
        float v = b5[lane];
        for (int k = 0; k < 10; k++) v = fmaf(W5[lane * 10 + k], sB_[w][k], v);
        sll[w][lane] = v;
        accw[w][lane] = 0.f;
    }
    __syncwarp();
    if (lane < 30) {
        int s = lane / 3, cc = lane % 3;
        const float* u = unif + ((w * 10 + s) * 3 + cc) * 5;
        float z[5];
        float mx = -1e30f;
#pragma unroll
        for (int m = 0; m < 5; m++) {
            float g = -logf(-logf(u[m] + 1e-20f));
            z[m] = (g + sll[w][cc * 5 + m]) * 10.0f;   // /TEMP, TEMP=0.1
            mx = fmaxf(mx, z[m]);
        }
        float sum = 0.f;
#pragma unroll
        for (int m = 0; m < 5; m++) { z[m] = expf(z[m] - mx); sum += z[m]; }
        float inv = 0.1f / sum;                        // /sum, then mean over ns=10
#pragma unroll
        for (int m = 0; m < 5; m++) atomicAdd(&accw[w][cc * 5 + m], z[m] * inv);
    }
    __syncwarp();
    if (lane < 15) g_w[w * 15 + lane] = accw[w][lane];
}

// ====== Kernel D2: symmetric weighted output, triangular 32i x 64j tiles ======
__global__ void __launch_bounds__(256, 2) kD2(const float* __restrict__ xc,
                                              const float* __restrict__ inv_std,
                                              const float* __restrict__ likerr,
                                              float* __restrict__ out) {
    int J = blockIdx.x, I = blockIdx.y;
    int half = I >> 1;
    if (J < half) return;
    bool mir = (J > half);
    int b  = blockIdx.z;
    int i0 = I * 32;
    int j0 = J * 64;

    __shared__ float2 s_wci[3][5][32];   // premultiplied by mixture weight
    __shared__ float4 s_cj[3][3][64];    // [c][group][jl]: (m0,m1),(m2,m3),(m4,xj)
    __shared__ float  s_xi[3][32];
    __shared__ float  s_diag[3];
    __shared__ __align__(16) float s_m[64 * 100];  // mirror staging: row jl, 96 cols, pitch 100

    int tx = threadIdx.x, ty = threadIdx.y;
    int tid = ty * 16 + tx;

    for (int idx = tid; idx < 480; idx += 256) {
        int c = idx / 160, r = idx % 160, m = r / 32, ii = r % 32;
        float2 v = g_cs[((b * 3 + c) * 5 + m) * 768 + i0 + ii];
        float wv = g_w[b * 15 + c * 5 + m];
        s_wci[c][m][ii] = make_float2(v.x * wv, v.y * wv);
    }
    if (tid < 192) {
        int c = tid / 64, jl = tid % 64; int j = j0 + jl;
        const float2* csb = g_cs + ((size_t)(b * 3 + c) * 5) * 768;
        float2 m0 = csb[j], m1 = csb[768 + j], m2 = csb[2 * 768 + j],
               m3 = csb[3 * 768 + j], m4 = csb[4 * 768 + j];
        float xj = xc[(b * 768 + j) * 3 + c];
        s_cj[c][0][jl] = make_float4(m0.x, m0.y, m1.x, m1.y);
        s_cj[c][1][jl] = make_float4(m2.x, m2.y, m3.x, m3.y);
        s_cj[c][2][jl] = make_float4(m4.x, m4.y, xj, 0.f);
    }
    if (tid < 96) { int c = tid / 32, ii = tid % 32; s_xi[c][ii] = xc[(b * 768 + i0 + ii) * 3 + c]; }
    if (tid < 3) { float l = fminf(fmaxf(likerr[tid], 0.1f), 1.0f); s_diag[tid] = ZITTERF + l * l; }

    float a2[5];
#pragma unroll
    for (int m = 0; m < 5; m++) { float s = inv_std[m]; a2[m] = KEXP * s * s; }

    __syncthreads();

    float2 wci[2][3][5]; float xi[2][3];
#pragma unroll
    for (int r = 0; r < 2; r++)
#pragma unroll
        for (int c = 0; c < 3; c++) {
            xi[r][c] = s_xi[c][ty + 16 * r];
#pragma unroll
            for (int m = 0; m < 5; m++) wci[r][c][m] = s_wci[c][m][ty + 16 * r];
        }

#pragma unroll
    for (int jj = 0; jj < 4; jj++) {
        int jl = tx + 16 * jj; int j = j0 + jl;
        float acc[2][3];
#pragma unroll
        for (int c = 0; c < 3; c++) {
            float4 g0 = s_cj[c][0][jl], g1 = s_cj[c][1][jl], g2 = s_cj[c][2][jl];
            float xj = g2.z;
#pragma unroll
            for (int r = 0; r < 2; r++) {
                float d = xi[r][c] - xj, d2 = d * d;
                float a;
                a = ex2f(a2[0] * d2) * fmaf(wci[r][c][0].x, g0.x, wci[r][c][0].y * g0.y);
                a = fmaf(ex2f(a2[1] * d2), fmaf(wci[r][c][1].x, g0.z, wci[r][c][1].y * g0.w), a);
                a = fmaf(ex2f(a2[2] * d2), fmaf(wci[r][c][2].x, g1.x, wci[r][c][2].y * g1.y), a);
                a = fmaf(ex2f(a2[3] * d2), fmaf(wci[r][c][3].x, g1.z, wci[r][c][3].y * g1.w), a);
                a = fmaf(ex2f(a2[4] * d2), fmaf(wci[r][c][4].x, g2.x, wci[r][c][4].y * g2.y), a);
                acc[r][c] = a;
            }
        }
#pragma unroll
        for (int r = 0; r < 2; r++) {
            int i = i0 + ty + 16 * r;
            if (i == j) { acc[r][0] += s_diag[0]; acc[r][1] += s_diag[1]; acc[r][2] += s_diag[2]; }
            float* o = out + ((size_t)(b * 768 + i) * 768 + j) * 3;
            o[0] = acc[r][0]; o[1] = acc[r][1]; o[2] = acc[r][2];
            if (mir) {
                int col = (ty + 16 * r) * 3;
                s_m[jl * 100 + col]     = acc[r][0];
                s_m[jl * 100 + col + 1] = acc[r][1];
                s_m[jl * 100 + col + 2] = acc[r][2];
            }
        }
    }

    if (mir) {
        __syncthreads();
        int jl = tid >> 2, q = tid & 3;
        const float* src = s_m + jl * 100 + 24 * q;
        float* dst = out + ((size_t)(b * 768 + j0 + jl)) * 2304 + i0 * 3 + 24 * q;
#pragma unroll
        for (int k = 0; k < 6; k++)
            ((float4*)dst)[k] = ((const float4*)src)[k];
    }
}

extern "C" void kernel_launch(void* const* d_in, const int* in_sizes, int n_in,
                              void* d_out, int out_size) {
    const float* xc      = (const float*)d_in[0];
    const float* yc      = (const float*)d_in[1];
    const float* mu      = (const float*)d_in[2];
    const float* inv_std = (const float*)d_in[3];
    const float* likerr  = (const float*)d_in[4];
    const float* unif    = (const float*)d_in[5];
    const float* W1 = (const float*)d_in[6];
    const float* b1 = (const float*)d_in[7];
    const float* W2 = (const float*)d_in[8];
    const float* b2 = (const float*)d_in[9];
    const float* W3 = (const float*)d_in[10];
    const float* b3 = (const float*)d_in[11];
    const float* W4 = (const float*)d_in[12];
    const float* b4 = (const float*)d_in[13];
    const float* W5 = (const float*)d_in[14];
    const float* b5 = (const float*)d_in[15];
    float* out = (float*)d_out;

    kA<<<360, 256>>>(xc, mu);
    kB2<<<dim3(12, 24, 24), dim3(16, 16)>>>(xc, yc, inv_std);
    kB3f<<<24, 256>>>(yc, W1, b1, unif, W2, b2, W3, b3, W4, b4, W5, b5);
    kD2<<<dim3(12, 24, 8), dim3(16, 16)>>>(xc, inv_std, likerr, out);
}